// round 1
// baseline (speedup 1.0000x reference)
#include <cuda_runtime.h>
#include <math.h>

#define S_ 1024
#define B_ 8
#define D_ 1024
#define H_ 16
#define DK_ 64
#define F_ 4096
#define M_TOK (S_*B_)   // 8192
#define QB 8

// ---------------- scratch (device globals; no allocation) ----------------
__device__ float g_qkin [8388608];   // [M,D] batch-first: src+pos
__device__ float g_srcbf[8388608];   // [M,D] batch-first: src
__device__ float g_Q    [8388608];
__device__ float g_K    [8388608];
__device__ float g_V    [8388608];
__device__ float g_ctx  [8388608];
__device__ float g_ao   [8388608];   // attn projection output (batch-first)
__device__ float g_x    [8388608];   // after LN1 (batch-first)
__device__ float g_h1   [33554432];  // [M,F]
__device__ float g_f2   [8388608];   // FFN output (batch-first)

// ---------------- prep: [S,B,D] -> batch-first [B,S,D]; qk_in = src+pos ----
__global__ void prep_kernel(const float* __restrict__ src, const float* __restrict__ pos,
                            float* __restrict__ qkin, float* __restrict__ srcbf)
{
    size_t idx = (size_t)blockIdx.x * blockDim.x + threadIdx.x;
    if (idx >= (size_t)S_ * B_ * D_) return;
    int d = (int)(idx % D_);
    size_t sb = idx / D_;
    int b = (int)(sb % B_);
    int s = (int)(sb / B_);
    size_t o = ((size_t)(b * S_ + s)) * D_ + d;
    float sv = src[idx];
    qkin[o]  = sv + pos[idx];
    srcbf[o] = sv;
}

// ---------------- GEMM: C[M,N] = A[M,K] @ W[K,N] + bias (+ReLU) ------------
// 64x64 block tile, BK=16, 256 threads, 4x4 per-thread register tile.
__global__ void gemm_kernel(const float* __restrict__ A, const float* __restrict__ W,
                            const float* __restrict__ bias, float* __restrict__ C,
                            int Mm, int Nn, int Kk, int relu)
{
    __shared__ float As[16][68];
    __shared__ float Ws[16][68];
    int tid = threadIdx.x;
    int tx = tid & 15, ty = tid >> 4;
    int row0 = blockIdx.y * 64, col0 = blockIdx.x * 64;
    float acc[4][4] = {};

    for (int k0 = 0; k0 < Kk; k0 += 16) {
        int e = tid * 4;
        {   // A tile: 64 rows x 16 cols
            int r = e >> 4, c = e & 15;
            const float4 av = *(const float4*)(A + (size_t)(row0 + r) * Kk + k0 + c);
            As[c + 0][r] = av.x; As[c + 1][r] = av.y;
            As[c + 2][r] = av.z; As[c + 3][r] = av.w;
        }
        {   // W tile: 16 rows x 64 cols
            int r = e >> 6, c = e & 63;
            *(float4*)(&Ws[r][c]) = *(const float4*)(W + (size_t)(k0 + r) * Nn + col0 + c);
        }
        __syncthreads();
        #pragma unroll
        for (int kk = 0; kk < 16; kk++) {
            float4 a = *(const float4*)(&As[kk][ty * 4]);
            float4 w = *(const float4*)(&Ws[kk][tx * 4]);
            float av[4] = {a.x, a.y, a.z, a.w};
            float wv[4] = {w.x, w.y, w.z, w.w};
            #pragma unroll
            for (int i = 0; i < 4; i++)
                #pragma unroll
                for (int j = 0; j < 4; j++)
                    acc[i][j] += av[i] * wv[j];
        }
        __syncthreads();
    }
    #pragma unroll
    for (int i = 0; i < 4; i++) {
        int r = row0 + ty * 4 + i;
        #pragma unroll
        for (int j = 0; j < 4; j++) {
            int c = col0 + tx * 4 + j;
            float v = acc[i][j] + bias[c];
            if (relu) v = fmaxf(v, 0.0f);
            C[(size_t)r * Nn + c] = v;
        }
    }
}

// ---------------- fused attention: scores + softmax + attn-store + ctx -----
// One block handles QB=8 query rows of one (b,h). 256 threads.
__global__ void attn_kernel(const float* __restrict__ Q, const float* __restrict__ Kp,
                            const float* __restrict__ V, float* __restrict__ ctx,
                            float* __restrict__ attn_g)
{
    int b = blockIdx.z, h = blockIdx.y;
    int q0 = blockIdx.x * QB;
    __shared__ float qs[QB][64];
    __shared__ float sc[QB][S_];
    __shared__ float red[256];
    int tid = threadIdx.x;

    for (int i = tid; i < QB * 64; i += 256) {
        int qi = i >> 6, d = i & 63;
        qs[qi][d] = Q[((size_t)(b * S_ + q0 + qi)) * D_ + h * 64 + d];
    }
    __syncthreads();

    // scores: each thread handles a stripe of k, all QB queries
    for (int k = tid; k < S_; k += 256) {
        const float4* kr = (const float4*)(Kp + ((size_t)(b * S_ + k)) * D_ + h * 64);
        float acc[QB];
        #pragma unroll
        for (int qi = 0; qi < QB; qi++) acc[qi] = 0.0f;
        #pragma unroll
        for (int d4 = 0; d4 < 16; d4++) {
            float4 kv = kr[d4];
            #pragma unroll
            for (int qi = 0; qi < QB; qi++) {
                float4 qv = *(const float4*)(&qs[qi][d4 * 4]);
                acc[qi] += qv.x * kv.x + qv.y * kv.y + qv.z * kv.z + qv.w * kv.w;
            }
        }
        #pragma unroll
        for (int qi = 0; qi < QB; qi++) sc[qi][k] = acc[qi] * 0.125f;
    }
    __syncthreads();

    // softmax: one warp per query row
    {
        int w = tid >> 5, lane = tid & 31;
        float mx = -1e30f;
        for (int k = lane; k < S_; k += 32) mx = fmaxf(mx, sc[w][k]);
        #pragma unroll
        for (int o = 16; o > 0; o >>= 1) mx = fmaxf(mx, __shfl_xor_sync(0xffffffffu, mx, o));
        float sum = 0.0f;
        for (int k = lane; k < S_; k += 32) {
            float e = expf(sc[w][k] - mx);
            sc[w][k] = e; sum += e;
        }
        #pragma unroll
        for (int o = 16; o > 0; o >>= 1) sum += __shfl_xor_sync(0xffffffffu, sum, o);
        float inv = 1.0f / sum;
        for (int k = lane; k < S_; k += 32) {
            float p = sc[w][k] * inv;
            sc[w][k] = p;
            if (attn_g)
                attn_g[(((size_t)(b * H_ + h)) * S_ + (q0 + w)) * S_ + k] = p;
        }
    }
    __syncthreads();

    // ctx = attn @ V : thread (d, slice) accumulates all QB rows
    {
        int d = tid & 63, sl = tid >> 6;   // 4 slices of 256 k each
        float acc[QB];
        #pragma unroll
        for (int qi = 0; qi < QB; qi++) acc[qi] = 0.0f;
        int k0 = sl * 256;
        for (int k = k0; k < k0 + 256; ++k) {
            float v = V[((size_t)(b * S_ + k)) * D_ + h * 64 + d];
            #pragma unroll
            for (int qi = 0; qi < QB; qi++) acc[qi] += sc[qi][k] * v;
        }
        #pragma unroll
        for (int qi = 0; qi < QB; qi++) {
            __syncthreads();
            red[tid] = acc[qi];
            __syncthreads();
            if (tid < 64)
                ctx[((size_t)(b * S_ + q0 + qi)) * D_ + h * 64 + tid] =
                    red[tid] + red[tid + 64] + red[tid + 128] + red[tid + 192];
        }
    }
}

// ---------------- fused add + LayerNorm ----------------
// in1 layout selectable ([S,B,D] vs batch-first), in2 batch-first, out selectable.
__global__ void ln_kernel(const float* __restrict__ in1, int in1_sbd,
                          const float* __restrict__ in2,
                          const float* __restrict__ gamma, const float* __restrict__ beta,
                          float* __restrict__ out, int out_sbd)
{
    int m = blockIdx.x;
    int b = m / S_, s = m % S_;
    size_t sbd_off = ((size_t)(s * B_ + b)) * D_;
    size_t bf_off  = (size_t)m * D_;
    const float* p1 = in1 + (in1_sbd ? sbd_off : bf_off);
    const float* p2 = in2 + bf_off;
    float* po = out + (out_sbd ? sbd_off : bf_off);

    __shared__ float xs[D_];
    __shared__ float r1[256], r2[256];
    int tid = threadIdx.x;
    float s1 = 0.0f, s2 = 0.0f;
    for (int d = tid; d < D_; d += 256) {
        float v = p1[d] + p2[d];
        xs[d] = v; s1 += v; s2 += v * v;
    }
    r1[tid] = s1; r2[tid] = s2;
    __syncthreads();
    for (int st = 128; st > 0; st >>= 1) {
        if (tid < st) { r1[tid] += r1[tid + st]; r2[tid] += r2[tid + st]; }
        __syncthreads();
    }
    float mean = r1[0] * (1.0f / D_);
    float var  = r2[0] * (1.0f / D_) - mean * mean;
    float rstd = rsqrtf(var + 1e-5f);
    for (int d = tid; d < D_; d += 256)
        po[d] = (xs[d] - mean) * rstd * gamma[d] + beta[d];
}

// ---------------- launch ----------------
extern "C" void kernel_launch(void* const* d_in, const int* in_sizes, int n_in,
                              void* d_out, int out_size)
{
    static float *qkin = nullptr, *srcbf, *Qb, *Kb, *Vb, *ctx, *ao, *x, *h1, *f2;
    if (!qkin) {
        cudaGetSymbolAddress((void**)&qkin,  g_qkin);
        cudaGetSymbolAddress((void**)&srcbf, g_srcbf);
        cudaGetSymbolAddress((void**)&Qb,    g_Q);
        cudaGetSymbolAddress((void**)&Kb,    g_K);
        cudaGetSymbolAddress((void**)&Vb,    g_V);
        cudaGetSymbolAddress((void**)&ctx,   g_ctx);
        cudaGetSymbolAddress((void**)&ao,    g_ao);
        cudaGetSymbolAddress((void**)&x,     g_x);
        cudaGetSymbolAddress((void**)&h1,    g_h1);
        cudaGetSymbolAddress((void**)&f2,    g_f2);
    }

    const float* src = (const float*)d_in[0];
    const float* pos = (const float*)d_in[1];
    const float* Wq  = (const float*)d_in[2];
    const float* bq  = (const float*)d_in[3];
    const float* Wk  = (const float*)d_in[4];
    const float* bk  = (const float*)d_in[5];
    const float* Wv  = (const float*)d_in[6];
    const float* bv  = (const float*)d_in[7];
    const float* Wo  = (const float*)d_in[8];
    const float* bo  = (const float*)d_in[9];
    const float* W1  = (const float*)d_in[10];
    const float* b1  = (const float*)d_in[11];
    const float* W2  = (const float*)d_in[12];
    const float* b2  = (const float*)d_in[13];
    const float* g1  = (const float*)d_in[14];
    const float* be1 = (const float*)d_in[15];
    const float* g2  = (const float*)d_in[16];
    const float* be2 = (const float*)d_in[17];

    float* out = (float*)d_out;
    float* attn_g = nullptr;
    long long need = (long long)S_ * B_ * D_ + (long long)B_ * H_ * S_ * S_;
    if ((long long)out_size >= need)
        attn_g = out + (size_t)S_ * B_ * D_;

    // 1) prep
    {
        size_t total = (size_t)S_ * B_ * D_;
        prep_kernel<<<(unsigned)((total + 255) / 256), 256>>>(src, pos, qkin, srcbf);
    }

    dim3 gD(D_ / 64, M_TOK / 64);   // N=1024 GEMMs
    dim3 gF(F_ / 64, M_TOK / 64);   // N=4096 GEMM

    // 2) QKV projections
    gemm_kernel<<<gD, 256>>>(qkin,  Wq, bq, Qb, M_TOK, D_, D_, 0);
    gemm_kernel<<<gD, 256>>>(qkin,  Wk, bk, Kb, M_TOK, D_, D_, 0);
    gemm_kernel<<<gD, 256>>>(srcbf, Wv, bv, Vb, M_TOK, D_, D_, 0);

    // 3) attention (scores + softmax + attn out + ctx)
    attn_kernel<<<dim3(S_ / QB, H_, B_), 256>>>(Qb, Kb, Vb, ctx, attn_g);

    // 4) output projection
    gemm_kernel<<<gD, 256>>>(ctx, Wo, bo, ao, M_TOK, D_, D_, 0);

    // 5) LN1: x = LN(src + attn_out)   (src is [S,B,D]; out batch-first)
    ln_kernel<<<M_TOK, 256>>>(src, 1, ao, g1, be1, x, 0);

    // 6) FFN
    gemm_kernel<<<gF, 256>>>(x,  W1, b1, h1, M_TOK, F_, D_, 1);
    gemm_kernel<<<gD, 256>>>(h1, W2, b2, f2, M_TOK, D_, F_, 0);

    // 7) LN2 -> output in [S,B,D]
    ln_kernel<<<M_TOK, 256>>>(x, 0, f2, g2, be2, out, 1);
}

// round 2
// speedup vs baseline: 5.1801x; 5.1801x over previous
#include <cuda_runtime.h>
#include <math.h>

#define S_ 1024
#define B_ 8
#define D_ 1024
#define H_ 16
#define F_ 4096
#define M_TOK (S_*B_)   // 8192

// ---------------- scratch (device globals; no allocation) ----------------
__device__ float g_qkin[8388608];    // [M,D] batch-first src+pos (tf32-rounded)
__device__ float g_srcbf[8388608];   // [M,D] batch-first src (tf32-rounded)
__device__ float g_Q[8388608];       // Q projection (rounded)
__device__ float g_Kt[8388608];      // K projection, per-head transposed [B,H,64,S] (rounded)
__device__ float g_V[8388608];       // V projection (rounded)
__device__ float g_ctx[8388608];     // attention context (rounded)
__device__ float g_ao[8388608];      // attn out-projection
__device__ float g_x[8388608];       // LN1 output (rounded)
__device__ float g_h1[33554432];     // FFN hidden [M,F] (rounded)
__device__ float g_f2[8388608];      // FFN output
__device__ float g_wr[12582912];     // rounded weights: Wq,Wk,Wv,Wo(4x1M) W1(4M) W2(4M)
__device__ float g_attn_fb[134217728]; // fallback attn buffer if d_out lacks attn

// ---------------- helpers ----------------
__device__ __forceinline__ float tf32r(float v) {
    unsigned r; asm("cvt.rna.tf32.f32 %0, %1;" : "=r"(r) : "f"(v));
    return __uint_as_float(r);
}
__device__ __forceinline__ void cp16(void* s, const void* g) {
    unsigned sa = (unsigned)__cvta_generic_to_shared(s);
    asm volatile("cp.async.ca.shared.global [%0], [%1], 16;" :: "r"(sa), "l"(g));
}
#define CP_COMMIT() asm volatile("cp.async.commit_group;")
#define CP_WAIT0()  asm volatile("cp.async.wait_group 0;")
#define CP_WAIT1()  asm volatile("cp.async.wait_group 1;")

__device__ __forceinline__ void mma_tf32(float* d, const unsigned* a, const unsigned* b) {
    asm volatile(
        "mma.sync.aligned.m16n8k8.row.col.f32.tf32.tf32.f32 "
        "{%0,%1,%2,%3}, {%4,%5,%6,%7}, {%8,%9}, {%0,%1,%2,%3};"
        : "+f"(d[0]), "+f"(d[1]), "+f"(d[2]), "+f"(d[3])
        : "r"(a[0]), "r"(a[1]), "r"(a[2]), "r"(a[3]), "r"(b[0]), "r"(b[1]));
}

// ---------------- tf32 tensor-core GEMM ----------------
// C[M,N] = alpha * A[M,K] @ W[K,N] + bias, optional ReLU, optional tf32 rounding
// of the output, optional per-head-transposed write (for the K projection).
// Block tile 128 x BN, BK=32, 256 threads (8 warps as 4x2), warp tile 32 x BN/2.
// Inputs A and W MUST be pre-rounded to tf32-representable floats.
template<int BN>
__global__ void __launch_bounds__(256, 2) mma_gemm(
    const float* __restrict__ A, const float* __restrict__ W,
    const float* __restrict__ bias, float* __restrict__ C,
    int K, int lda, int ldb, int ldc, int zdiv,
    long long sAh, long long sAl, long long sBh, long long sBl,
    long long sCh, long long sCl,
    float alpha, int relu, int rnd, int ktmode)
{
    constexpr int WN  = BN / 2;       // warp n-tile
    constexpr int NI  = BN / 16;      // n8 fragments per warp
    constexpr int F4W = BN / 4;       // float4 per W-tile row
    constexpr int NW  = BN / 32;      // W float4 chunks per thread
    constexpr int BNS = BN + 8;       // padded W smem row stride
    constexpr int AS_SZ = 128 * 36;
    constexpr int WS_SZ = 32 * BNS;

    extern __shared__ float smem[];
    float* As0 = smem;
    float* Ws0 = smem + 2 * AS_SZ;

    int tid = threadIdx.x;
    int wid = tid >> 5, lane = tid & 31;
    int wm = wid & 3, wn = wid >> 2;
    int m0 = blockIdx.y * 128;
    int n0 = blockIdx.x * BN;
    int z  = blockIdx.z;

    const float* Ag = A + (long long)(z / zdiv) * sAh + (long long)(z % zdiv) * sAl
                        + (size_t)m0 * lda;
    const float* Wg = W + (long long)(z / zdiv) * sBh + (long long)(z % zdiv) * sBl + n0;
    float* Cg = C + (long long)(z / zdiv) * sCh + (long long)(z % zdiv) * sCl;

    float acc[2][NI][4];
    #pragma unroll
    for (int mi = 0; mi < 2; mi++)
        #pragma unroll
        for (int ni = 0; ni < NI; ni++)
            #pragma unroll
            for (int j = 0; j < 4; j++) acc[mi][ni][j] = 0.0f;

    auto load_stage = [&](int buf, int k0) {
        float* as = As0 + buf * AS_SZ;
        float* ws = Ws0 + buf * WS_SZ;
        #pragma unroll
        for (int i = 0; i < 4; i++) {           // A: 128x32 floats
            int c = tid + i * 256;
            int r = c >> 3, c4 = (c & 7) * 4;
            cp16(&as[r * 36 + c4], Ag + (size_t)r * lda + k0 + c4);
        }
        #pragma unroll
        for (int i = 0; i < NW; i++) {          // W: 32xBN floats
            int c = tid + i * 256;
            int r = c / F4W, c4 = (c % F4W) * 4;
            cp16(&ws[r * BNS + c4], Wg + (size_t)(k0 + r) * ldb + c4);
        }
    };

    int nk = K >> 5;
    load_stage(0, 0);
    CP_COMMIT();

    for (int kt = 0; kt < nk; kt++) {
        if (kt + 1 < nk) {
            load_stage((kt + 1) & 1, (kt + 1) << 5);
            CP_COMMIT();
            CP_WAIT1();
        } else {
            CP_WAIT0();
        }
        __syncthreads();

        const float* as = As0 + (kt & 1) * AS_SZ;
        const float* ws = Ws0 + (kt & 1) * WS_SZ;
        #pragma unroll
        for (int kk = 0; kk < 32; kk += 8) {
            unsigned afr[2][4];
            #pragma unroll
            for (int mi = 0; mi < 2; mi++) {
                int r = wm * 32 + mi * 16 + (lane >> 2);
                int c = kk + (lane & 3);
                afr[mi][0] = __float_as_uint(as[r * 36 + c]);
                afr[mi][1] = __float_as_uint(as[(r + 8) * 36 + c]);
                afr[mi][2] = __float_as_uint(as[r * 36 + c + 4]);
                afr[mi][3] = __float_as_uint(as[(r + 8) * 36 + c + 4]);
            }
            #pragma unroll
            for (int ni = 0; ni < NI; ni++) {
                int n = wn * WN + ni * 8 + (lane >> 2);
                unsigned bfr[2];
                bfr[0] = __float_as_uint(ws[(kk + (lane & 3)) * BNS + n]);
                bfr[1] = __float_as_uint(ws[(kk + (lane & 3) + 4) * BNS + n]);
                #pragma unroll
                for (int mi = 0; mi < 2; mi++)
                    mma_tf32(acc[mi][ni], afr[mi], bfr);
            }
        }
        __syncthreads();
    }

    // epilogue
    #pragma unroll
    for (int mi = 0; mi < 2; mi++) {
        #pragma unroll
        for (int ni = 0; ni < NI; ni++) {
            int rbase = m0 + wm * 32 + mi * 16 + (lane >> 2);
            int cc = n0 + wn * WN + ni * 8 + (lane & 3) * 2;
            float b0 = 0.0f, b1 = 0.0f;
            if (bias) { b0 = bias[cc]; b1 = bias[cc + 1]; }
            #pragma unroll
            for (int h2 = 0; h2 < 2; h2++) {
                int row = rbase + h2 * 8;
                float v0 = fmaf(acc[mi][ni][h2 * 2 + 0], alpha, b0);
                float v1 = fmaf(acc[mi][ni][h2 * 2 + 1], alpha, b1);
                if (relu) { v0 = fmaxf(v0, 0.0f); v1 = fmaxf(v1, 0.0f); }
                if (rnd)  { v0 = tf32r(v0); v1 = tf32r(v1); }
                if (ktmode) {
                    // write K transposed per head: Kt[b][h][d][s]
                    int b = row >> 10, s = row & 1023;
                    int h = cc >> 6, d = cc & 63;
                    Cg[((size_t)((b * H_ + h) * 64 + d) << 10) + s] = v0;
                    Cg[((size_t)((b * H_ + h) * 64 + d + 1) << 10) + s] = v1;
                } else {
                    *(float2*)(Cg + (size_t)row * ldc + cc) = make_float2(v0, v1);
                }
            }
        }
    }
}

// ---------------- prep: [S,B,D] -> batch-first; qk_in = src+pos (rounded) ---
__global__ void prep_kernel(const float* __restrict__ src, const float* __restrict__ pos,
                            float* __restrict__ qkin, float* __restrict__ srcbf)
{
    size_t idx = (size_t)blockIdx.x * blockDim.x + threadIdx.x;
    if (idx >= (size_t)S_ * B_ * D_) return;
    int d = (int)(idx % D_);
    size_t sb = idx / D_;
    int b = (int)(sb % B_);
    int s = (int)(sb / B_);
    size_t o = ((size_t)(b * S_ + s)) * D_ + d;
    float sv = src[idx];
    qkin[o]  = tf32r(sv + pos[idx]);
    srcbf[o] = tf32r(sv);
}

// ---------------- round weights to tf32-representable floats ----------------
__global__ void round_kernel(const float* __restrict__ in, float* __restrict__ out, int n)
{
    int i = blockIdx.x * blockDim.x + threadIdx.x;
    if (i < n) out[i] = tf32r(in[i]);
}

// ---------------- in-place row softmax over attn buffer, round probs --------
__global__ void softmax_kernel(float* __restrict__ a)
{
    float4* p = (float4*)(a + ((size_t)blockIdx.x << 10));
    int tid = threadIdx.x, wid = tid >> 5, lane = tid & 31;
    __shared__ float red[16];
    float4 v = p[tid];
    float m = fmaxf(fmaxf(v.x, v.y), fmaxf(v.z, v.w));
    #pragma unroll
    for (int o = 16; o > 0; o >>= 1) m = fmaxf(m, __shfl_xor_sync(0xffffffffu, m, o));
    if (lane == 0) red[wid] = m;
    __syncthreads();
    m = red[0];
    #pragma unroll
    for (int i = 1; i < 8; i++) m = fmaxf(m, red[i]);
    v.x = __expf(v.x - m); v.y = __expf(v.y - m);
    v.z = __expf(v.z - m); v.w = __expf(v.w - m);
    float s = v.x + v.y + v.z + v.w;
    #pragma unroll
    for (int o = 16; o > 0; o >>= 1) s += __shfl_xor_sync(0xffffffffu, s, o);
    if (lane == 0) red[8 + wid] = s;
    __syncthreads();
    s = 0.0f;
    #pragma unroll
    for (int i = 0; i < 8; i++) s += red[8 + i];
    float inv = 1.0f / s;
    v.x = tf32r(v.x * inv); v.y = tf32r(v.y * inv);
    v.z = tf32r(v.z * inv); v.w = tf32r(v.w * inv);
    p[tid] = v;
}

// ---------------- fused add + LayerNorm ----------------
__global__ void ln_kernel(const float* __restrict__ in1, int in1_sbd,
                          const float* __restrict__ in2,
                          const float* __restrict__ gamma, const float* __restrict__ beta,
                          float* __restrict__ out, int out_sbd, int rnd)
{
    int m = blockIdx.x;
    int b = m / S_, s = m % S_;
    size_t sbd_off = ((size_t)(s * B_ + b)) * D_;
    size_t bf_off  = (size_t)m * D_;
    const float* p1 = in1 + (in1_sbd ? sbd_off : bf_off);
    const float* p2 = in2 + bf_off;
    float* po = out + (out_sbd ? sbd_off : bf_off);

    __shared__ float xs[D_];
    __shared__ float r1[256], r2[256];
    int tid = threadIdx.x;
    float s1 = 0.0f, s2 = 0.0f;
    for (int d = tid; d < D_; d += 256) {
        float v = p1[d] + p2[d];
        xs[d] = v; s1 += v; s2 += v * v;
    }
    r1[tid] = s1; r2[tid] = s2;
    __syncthreads();
    for (int st = 128; st > 0; st >>= 1) {
        if (tid < st) { r1[tid] += r1[tid + st]; r2[tid] += r2[tid + st]; }
        __syncthreads();
    }
    float mean = r1[0] * (1.0f / D_);
    float var  = r2[0] * (1.0f / D_) - mean * mean;
    float rstd = rsqrtf(var + 1e-5f);
    for (int d = tid; d < D_; d += 256) {
        float v = (xs[d] - mean) * rstd * gamma[d] + beta[d];
        po[d] = rnd ? tf32r(v) : v;
    }
}

// ---------------- launch ----------------
extern "C" void kernel_launch(void* const* d_in, const int* in_sizes, int n_in,
                              void* d_out, int out_size)
{
    static float *qkin = nullptr, *srcbf, *Qb, *Kt, *Vb, *ctx, *ao, *x, *h1, *f2,
                 *wr, *attn_fb;
    if (!qkin) {
        cudaGetSymbolAddress((void**)&qkin,  g_qkin);
        cudaGetSymbolAddress((void**)&srcbf, g_srcbf);
        cudaGetSymbolAddress((void**)&Qb,    g_Q);
        cudaGetSymbolAddress((void**)&Kt,    g_Kt);
        cudaGetSymbolAddress((void**)&Vb,    g_V);
        cudaGetSymbolAddress((void**)&ctx,   g_ctx);
        cudaGetSymbolAddress((void**)&ao,    g_ao);
        cudaGetSymbolAddress((void**)&x,     g_x);
        cudaGetSymbolAddress((void**)&h1,    g_h1);
        cudaGetSymbolAddress((void**)&f2,    g_f2);
        cudaGetSymbolAddress((void**)&wr,    g_wr);
        cudaGetSymbolAddress((void**)&attn_fb, g_attn_fb);
    }

    const float* src = (const float*)d_in[0];
    const float* pos = (const float*)d_in[1];
    const float* Wq  = (const float*)d_in[2];
    const float* bq  = (const float*)d_in[3];
    const float* Wk  = (const float*)d_in[4];
    const float* bk  = (const float*)d_in[5];
    const float* Wv  = (const float*)d_in[6];
    const float* bv  = (const float*)d_in[7];
    const float* Wo  = (const float*)d_in[8];
    const float* bo  = (const float*)d_in[9];
    const float* W1  = (const float*)d_in[10];
    const float* b1  = (const float*)d_in[11];
    const float* W2  = (const float*)d_in[12];
    const float* b2  = (const float*)d_in[13];
    const float* g1  = (const float*)d_in[14];
    const float* be1 = (const float*)d_in[15];
    const float* g2  = (const float*)d_in[16];
    const float* be2 = (const float*)d_in[17];

    float* out = (float*)d_out;
    long long need = (long long)S_ * B_ * D_ + (long long)B_ * H_ * S_ * S_;
    float* attn = ((long long)out_size >= need) ? out + (size_t)S_ * B_ * D_ : attn_fb;

    const int SM128 = (2 * 128 * 36 + 2 * 32 * 136) * 4;   // 71680 B
    const int SM64  = (2 * 128 * 36 + 2 * 32 * 72) * 4;    // 55296 B
    cudaFuncSetAttribute(mma_gemm<128>, cudaFuncAttributeMaxDynamicSharedMemorySize, SM128);
    cudaFuncSetAttribute(mma_gemm<64>,  cudaFuncAttributeMaxDynamicSharedMemorySize, SM64);

    // rounded weight copies
    float* wqr = wr;
    float* wkr = wr + 1048576;
    float* wvr = wr + 2097152;
    float* wor = wr + 3145728;
    float* w1r = wr + 4194304;
    float* w2r = wr + 8388608;
    round_kernel<<<4096, 256>>>(Wq, wqr, 1048576);
    round_kernel<<<4096, 256>>>(Wk, wkr, 1048576);
    round_kernel<<<4096, 256>>>(Wv, wvr, 1048576);
    round_kernel<<<4096, 256>>>(Wo, wor, 1048576);
    round_kernel<<<16384, 256>>>(W1, w1r, 4194304);
    round_kernel<<<16384, 256>>>(W2, w2r, 4194304);

    // prep
    prep_kernel<<<(unsigned)(((size_t)S_ * B_ * D_ + 255) / 256), 256>>>(src, pos, qkin, srcbf);

    const long long SD = (long long)S_ * D_;       // 1048576
    const long long SS = (long long)S_ * S_;       // 1048576

    // QKV projections (M=8192, N=1024, K=1024)
    mma_gemm<128><<<dim3(8, 64, 1), 256, SM128>>>(qkin, wqr, bq, Qb,
        1024, D_, D_, D_, 1, 0, 0, 0, 0, 0, 0, 1.0f, 0, 1, 0);
    mma_gemm<128><<<dim3(8, 64, 1), 256, SM128>>>(qkin, wkr, bk, Kt,
        1024, D_, D_, D_, 1, 0, 0, 0, 0, 0, 0, 1.0f, 0, 1, 1);
    mma_gemm<128><<<dim3(8, 64, 1), 256, SM128>>>(srcbf, wvr, bv, Vb,
        1024, D_, D_, D_, 1, 0, 0, 0, 0, 0, 0, 1.0f, 0, 1, 0);

    // scores = Q @ Kt / 8  -> attn buffer   (per (b,h): M=N=1024, K=64)
    mma_gemm<128><<<dim3(8, 8, B_ * H_), 256, SM128>>>(Qb, Kt, nullptr, attn,
        64, D_, S_, S_, H_,
        SD, 64,                 // A: Q per-batch, per-head col offset
        (long long)H_ * 65536, 65536,   // B: Kt head blocks
        (long long)H_ * SS, SS,         // C: attn
        0.125f, 0, 0, 0);

    // softmax in place (+ tf32 rounding of probs)
    softmax_kernel<<<B_ * H_ * S_, 256>>>(attn);

    // ctx = attn @ V   (per (b,h): M=1024, N=64, K=1024)
    mma_gemm<64><<<dim3(1, 8, B_ * H_), 256, SM64>>>(attn, Vb, nullptr, ctx,
        1024, S_, D_, D_, H_,
        (long long)H_ * SS, SS,
        SD, 64,
        SD, 64,
        1.0f, 0, 1, 0);

    // output projection
    mma_gemm<128><<<dim3(8, 64, 1), 256, SM128>>>(ctx, wor, bo, ao,
        1024, D_, D_, D_, 1, 0, 0, 0, 0, 0, 0, 1.0f, 0, 0, 0);

    // LN1: x = LN(src + ao)
    ln_kernel<<<M_TOK, 256>>>(src, 1, ao, g1, be1, x, 0, 1);

    // FFN
    mma_gemm<128><<<dim3(32, 64, 1), 256, SM128>>>(x, w1r, b1, h1,
        1024, D_, F_, F_, 1, 0, 0, 0, 0, 0, 0, 1.0f, 1, 1, 0);
    mma_gemm<128><<<dim3(8, 64, 1), 256, SM128>>>(h1, w2r, b2, f2,
        4096, F_, D_, D_, 1, 0, 0, 0, 0, 0, 0, 1.0f, 0, 0, 0);

    // LN2 -> out in [S,B,D]
    ln_kernel<<<M_TOK, 256>>>(x, 0, f2, g2, be2, out, 1, 0);
}